// round 1
// baseline (speedup 1.0000x reference)
#include <cuda_runtime.h>
#include <cuda_bf16.h>
#include <math.h>

#define BATCH 2
#define SEQ   2048
#define DIM   1024
#define NH    16
#define HD    64
#define NTOK  (BATCH * SEQ)          // 4096

// Scratch (allocation-free rule: __device__ globals)
__device__ float g_qkv[(size_t)NTOK * 3 * DIM];   // [4096, 3072]
__device__ float g_attn[(size_t)NTOK * DIM];      // [4096, 1024]

// ---------------------------------------------------------------------------
// SGEMM: C[M,N] = A[M,K] @ W[K,N] + bias[N]
// 128x128 tile, BK=16, 256 threads, 8x8 per-thread
// ---------------------------------------------------------------------------
__global__ __launch_bounds__(256)
void sgemm_bias_kernel(const float* __restrict__ A,
                       const float* __restrict__ W,
                       const float* __restrict__ bias,
                       float* __restrict__ C,
                       int M, int N, int K)
{
    __shared__ float As[16][128];
    __shared__ float Bs[16][128];

    const int tid = threadIdx.x;
    const int tx  = tid & 15;     // 0..15  (col groups)
    const int ty  = tid >> 4;     // 0..15  (row groups)
    const int m0  = blockIdx.y * 128;
    const int n0  = blockIdx.x * 128;

    float acc[8][8];
#pragma unroll
    for (int i = 0; i < 8; ++i)
#pragma unroll
        for (int j = 0; j < 8; ++j) acc[i][j] = 0.0f;

    for (int k0 = 0; k0 < K; k0 += 16) {
        // A tile: 128 rows x 16 cols -> store transposed As[col][row]
#pragma unroll
        for (int it = 0; it < 2; ++it) {
            int f  = tid + 256 * it;          // 0..511 float4 slots
            int r  = f >> 2;                  // 0..127
            int c4 = (f & 3) << 2;            // 0,4,8,12
            float4 v = *(const float4*)&A[(size_t)(m0 + r) * K + k0 + c4];
            As[c4 + 0][r] = v.x;
            As[c4 + 1][r] = v.y;
            As[c4 + 2][r] = v.z;
            As[c4 + 3][r] = v.w;
        }
        // W tile: 16 rows x 128 cols
#pragma unroll
        for (int it = 0; it < 2; ++it) {
            int f  = tid + 256 * it;
            int r  = f >> 5;                  // 0..15
            int c4 = (f & 31) << 2;           // 0..124
            *(float4*)&Bs[r][c4] = *(const float4*)&W[(size_t)(k0 + r) * N + n0 + c4];
        }
        __syncthreads();

#pragma unroll
        for (int kk = 0; kk < 16; ++kk) {
            float ra[8], rb[8];
#pragma unroll
            for (int i = 0; i < 8; ++i) ra[i] = As[kk][ty * 8 + i];
#pragma unroll
            for (int j = 0; j < 8; ++j) rb[j] = Bs[kk][tx * 8 + j];
#pragma unroll
            for (int i = 0; i < 8; ++i)
#pragma unroll
                for (int j = 0; j < 8; ++j)
                    acc[i][j] = fmaf(ra[i], rb[j], acc[i][j]);
        }
        __syncthreads();
    }

    // epilogue with bias
#pragma unroll
    for (int i = 0; i < 8; ++i) {
        size_t row = (size_t)(m0 + ty * 8 + i);
#pragma unroll
        for (int j = 0; j < 8; ++j) {
            int col = n0 + tx * 8 + j;
            C[row * N + col] = acc[i][j] + bias[col];
        }
    }
}

// ---------------------------------------------------------------------------
// Flash attention: one CTA per (b, h, 64-query block). 256 threads.
// K/V streamed in 64-key tiles. Online softmax.
// Thread layout: rq = tid>>3 (32 query-pairs), rc = tid&7 (8 col groups).
// Each thread owns rows {2rq, 2rq+1} x cols {rc*8 .. rc*8+7}.
// ---------------------------------------------------------------------------
#define LDP 65   // smem row pitch (pad)

__global__ __launch_bounds__(256)
void attn_kernel(const float* __restrict__ qkv, float* __restrict__ out)
{
    extern __shared__ float sm[];
    float* Qs = sm;                 // [64][65]
    float* Ks = sm + 64 * LDP;
    float* Vs = sm + 2 * 64 * LDP;
    float* Ps = sm + 3 * 64 * LDP;

    const int tid = threadIdx.x;
    const int bh  = blockIdx.y;
    const int b   = bh >> 4;
    const int h   = bh & 15;
    const int qb  = blockIdx.x;

    const size_t rowstride = 3 * DIM;
    const size_t base = (size_t)b * SEQ * rowstride;
    const int qoff = h * HD;
    const int koff = DIM + h * HD;
    const int voff = 2 * DIM + h * HD;
    const float scale = 0.125f;     // 1/sqrt(64)

    // load + pre-scale Q tile [64][64]
    for (int i = tid; i < 64 * 64; i += 256) {
        int r = i >> 6, c = i & 63;
        Qs[r * LDP + c] = qkv[base + (size_t)(qb * 64 + r) * rowstride + qoff + c] * scale;
    }

    const int rq = tid >> 3;
    const int rc = tid & 7;
    const int r0 = rq * 2, r1 = r0 + 1;

    float m0 = -1e30f, m1 = -1e30f;
    float l0 = 0.0f,   l1 = 0.0f;
    float o0[8], o1[8];
#pragma unroll
    for (int j = 0; j < 8; ++j) { o0[j] = 0.0f; o1[j] = 0.0f; }

    for (int kb = 0; kb < SEQ / 64; ++kb) {
        // load K,V tiles
        for (int i = tid; i < 64 * 64; i += 256) {
            int r = i >> 6, c = i & 63;
            size_t g = base + (size_t)(kb * 64 + r) * rowstride;
            Ks[r * LDP + c] = qkv[g + koff + c];
            Vs[r * LDP + c] = qkv[g + voff + c];
        }
        __syncthreads();

        // S = Q K^T   (2 rows x 8 cols per thread)
        float s0[8], s1[8];
#pragma unroll
        for (int j = 0; j < 8; ++j) { s0[j] = 0.0f; s1[j] = 0.0f; }
#pragma unroll 8
        for (int d = 0; d < 64; ++d) {
            float q0 = Qs[r0 * LDP + d];
            float q1 = Qs[r1 * LDP + d];
#pragma unroll
            for (int j = 0; j < 8; ++j) {
                float kv = Ks[(rc * 8 + j) * LDP + d];
                s0[j] = fmaf(q0, kv, s0[j]);
                s1[j] = fmaf(q1, kv, s1[j]);
            }
        }

        // online softmax: row max over this tile (8 lanes per row)
        float mx0 = s0[0], mx1 = s1[0];
#pragma unroll
        for (int j = 1; j < 8; ++j) { mx0 = fmaxf(mx0, s0[j]); mx1 = fmaxf(mx1, s1[j]); }
#pragma unroll
        for (int off = 1; off < 8; off <<= 1) {
            mx0 = fmaxf(mx0, __shfl_xor_sync(0xffffffffu, mx0, off));
            mx1 = fmaxf(mx1, __shfl_xor_sync(0xffffffffu, mx1, off));
        }
        float nm0 = fmaxf(m0, mx0);
        float nm1 = fmaxf(m1, mx1);
        float a0 = __expf(m0 - nm0);
        float a1 = __expf(m1 - nm1);

        float sum0 = 0.0f, sum1 = 0.0f;
#pragma unroll
        for (int j = 0; j < 8; ++j) {
            float p0 = __expf(s0[j] - nm0);
            float p1 = __expf(s1[j] - nm1);
            Ps[r0 * LDP + rc * 8 + j] = p0;
            Ps[r1 * LDP + rc * 8 + j] = p1;
            sum0 += p0; sum1 += p1;
        }
#pragma unroll
        for (int off = 1; off < 8; off <<= 1) {
            sum0 += __shfl_xor_sync(0xffffffffu, sum0, off);
            sum1 += __shfl_xor_sync(0xffffffffu, sum1, off);
        }
        l0 = l0 * a0 + sum0;
        l1 = l1 * a1 + sum1;
        m0 = nm0; m1 = nm1;
#pragma unroll
        for (int j = 0; j < 8; ++j) { o0[j] *= a0; o1[j] *= a1; }
        __syncthreads();   // Ps complete before PV

        // O += P @ V
#pragma unroll 8
        for (int k = 0; k < 64; ++k) {
            float p0 = Ps[r0 * LDP + k];
            float p1 = Ps[r1 * LDP + k];
#pragma unroll
            for (int j = 0; j < 8; ++j) {
                float v = Vs[k * LDP + rc * 8 + j];
                o0[j] = fmaf(p0, v, o0[j]);
                o1[j] = fmaf(p1, v, o1[j]);
            }
        }
        __syncthreads();   // before next tile overwrites K/V/P
    }

    float inv0 = 1.0f / l0;
    float inv1 = 1.0f / l1;
    size_t ob = ((size_t)b * SEQ + (size_t)qb * 64) * DIM + h * HD + rc * 8;
#pragma unroll
    for (int j = 0; j < 8; ++j) {
        out[ob + (size_t)r0 * DIM + j] = o0[j] * inv0;
        out[ob + (size_t)r1 * DIM + j] = o1[j] * inv1;
    }
}

// ---------------------------------------------------------------------------
extern "C" void kernel_launch(void* const* d_in, const int* in_sizes, int n_in,
                              void* d_out, int out_size)
{
    const float* x      = (const float*)d_in[0];
    const float* W_qkv  = (const float*)d_in[1];
    const float* b_qkv  = (const float*)d_in[2];
    const float* W_proj = (const float*)d_in[3];
    const float* b_proj = (const float*)d_in[4];
    float* out = (float*)d_out;

    float *qkv_buf, *attn_buf;
    cudaGetSymbolAddress((void**)&qkv_buf, g_qkv);
    cudaGetSymbolAddress((void**)&attn_buf, g_attn);

    static int smem_set = 0;
    const int attn_smem = 4 * 64 * LDP * sizeof(float);   // 66560 B
    if (!smem_set) {
        cudaFuncSetAttribute(attn_kernel, cudaFuncAttributeMaxDynamicSharedMemorySize,
                             attn_smem);
        smem_set = 1;
    }

    // 1) QKV projection: [4096,1024] @ [1024,3072] + b
    {
        dim3 grid(3 * DIM / 128, NTOK / 128);   // (24, 32)
        sgemm_bias_kernel<<<grid, 256>>>(x, W_qkv, b_qkv, qkv_buf,
                                         NTOK, 3 * DIM, DIM);
    }
    // 2) attention
    {
        dim3 grid(SEQ / 64, BATCH * NH);        // (32, 32)
        attn_kernel<<<grid, 256, attn_smem>>>(qkv_buf, attn_buf);
    }
    // 3) output projection: [4096,1024] @ [1024,1024] + b
    {
        dim3 grid(DIM / 128, NTOK / 128);       // (8, 32)
        sgemm_bias_kernel<<<grid, 256>>>(attn_buf, W_proj, b_proj, out,
                                         NTOK, DIM, DIM);
    }
}

// round 7
// speedup vs baseline: 4.2338x; 4.2338x over previous
#include <cuda_runtime.h>
#include <cuda_bf16.h>
#include <math.h>
#include <cstdint>

#define BATCH 2
#define SEQ   2048
#define DIM   1024
#define NH    16
#define HD    64
#define NTOK  4096

typedef __nv_bfloat16 bf16;
typedef unsigned short ushort_t;

// ---------------------------------------------------------------------------
// Scratch (__device__ globals; no allocation)
// ---------------------------------------------------------------------------
__device__ bf16 g_qh[(size_t)NTOK * 3 * DIM];   // qkv hi  [4096,3072]
__device__ bf16 g_ql[(size_t)NTOK * 3 * DIM];   // qkv lo
__device__ bf16 g_ah[(size_t)NTOK * DIM];       // GEMM A hi / attn out hi
__device__ bf16 g_al[(size_t)NTOK * DIM];       // GEMM A lo / attn out lo
__device__ bf16 g_bh[(size_t)3 * DIM * DIM];    // W^T hi [N,K]
__device__ bf16 g_bl[(size_t)3 * DIM * DIM];    // W^T lo

// ---------------------------------------------------------------------------
// HMMA m16n8k16 bf16 (arch-neutral, works on compute_103 base target)
// ---------------------------------------------------------------------------
__device__ __forceinline__ void mma16816(float* c, const uint32_t* a, const uint32_t* b) {
    asm volatile(
        "mma.sync.aligned.m16n8k16.row.col.f32.bf16.bf16.f32 "
        "{%0,%1,%2,%3}, {%4,%5,%6,%7}, {%8,%9}, {%0,%1,%2,%3};"
        : "+f"(c[0]), "+f"(c[1]), "+f"(c[2]), "+f"(c[3])
        : "r"(a[0]), "r"(a[1]), "r"(a[2]), "r"(a[3]), "r"(b[0]), "r"(b[1]));
}

// split two floats into packed bf16x2 hi and lo words
__device__ __forceinline__ void split2(float x, float y, uint32_t& hi, uint32_t& lo) {
    __nv_bfloat16 hx = __float2bfloat16(x);
    __nv_bfloat16 hy = __float2bfloat16(y);
    __nv_bfloat162 h2(hx, hy);
    __nv_bfloat162 l2(__float2bfloat16(x - __bfloat162float(hx)),
                      __float2bfloat16(y - __bfloat162float(hy)));
    hi = *(uint32_t*)&h2;
    lo = *(uint32_t*)&l2;
}

// ---------------------------------------------------------------------------
// fp32 -> bf16 hi/lo elementwise split
// ---------------------------------------------------------------------------
__global__ __launch_bounds__(256)
void split_kernel(const float* __restrict__ in, bf16* __restrict__ hi,
                  bf16* __restrict__ lo, int n4)
{
    int i = blockIdx.x * blockDim.x + threadIdx.x;
    if (i >= n4) return;
    float4 v = *(const float4*)&in[i * 4];
    float x[4] = {v.x, v.y, v.z, v.w};
    uint32_t h01, l01, h23, l23;
    split2(x[0], x[1], h01, l01);
    split2(x[2], x[3], h23, l23);
    *(uint32_t*)&hi[i * 4]     = h01;
    *(uint32_t*)&hi[i * 4 + 2] = h23;
    *(uint32_t*)&lo[i * 4]     = l01;
    *(uint32_t*)&lo[i * 4 + 2] = l23;
}

// W[K,N] fp32 -> hi/lo [N,K] bf16 (transpose + split)
__global__ __launch_bounds__(256)
void splitT_kernel(const float* __restrict__ W, bf16* __restrict__ hi,
                   bf16* __restrict__ lo, int K, int N)
{
    __shared__ float t[32][33];
    const int n0 = blockIdx.x * 32, k0 = blockIdx.y * 32;
    const int tx = threadIdx.x, ty = threadIdx.y;
#pragma unroll
    for (int r = 0; r < 4; ++r)
        t[ty + r * 8][tx] = W[(size_t)(k0 + ty + r * 8) * N + n0 + tx];
    __syncthreads();
#pragma unroll
    for (int r = 0; r < 4; ++r) {
        int nl = ty + r * 8;
        float x = t[tx][nl];
        __nv_bfloat16 h = __float2bfloat16(x);
        __nv_bfloat16 l = __float2bfloat16(x - __bfloat162float(h));
        size_t o = (size_t)(n0 + nl) * K + k0 + tx;
        hi[o] = h; lo[o] = l;
    }
}

// ---------------------------------------------------------------------------
// HMMA split-bf16 GEMM: C[M,N] = A@W + bias
// A: [M,K] hi/lo bf16; B = W^T: [N,K] hi/lo bf16.
// CTA 128x128, BK=64, 256 threads, warp tile 64x32.
// smem: 4 tiles of 128 rows x 72 bf16 (pitch 144B, word pitch 36).
// Outputs: fp32 C (optional) and/or bf16 hi/lo C (optional).
// ---------------------------------------------------------------------------
#define GEMM_SMEM (4 * 128 * 144)   // 73728 B

__global__ __launch_bounds__(256)
void hmma_gemm(const bf16* __restrict__ Ah, const bf16* __restrict__ Al,
               const bf16* __restrict__ Bh, const bf16* __restrict__ Bl,
               const float* __restrict__ bias,
               float* __restrict__ Cf, bf16* __restrict__ Chi, bf16* __restrict__ Clo,
               int M, int N, int K)
{
    extern __shared__ char sm[];
    char* tAh = sm;
    char* tAl = sm + 128 * 144;
    char* tBh = sm + 2 * 128 * 144;
    char* tBl = sm + 3 * 128 * 144;

    const int tid = threadIdx.x;
    const int w   = tid >> 5, lane = tid & 31;
    const int g   = lane >> 2, tg = lane & 3;
    const int wm  = w & 1;        // 0..1  (64-row block)
    const int wn  = w >> 1;       // 0..3  (32-col block)
    const int m0  = blockIdx.y * 128, n0 = blockIdx.x * 128;

    float acc[4][4][4];
#pragma unroll
    for (int a = 0; a < 4; ++a)
#pragma unroll
        for (int b = 0; b < 4; ++b)
#pragma unroll
            for (int c = 0; c < 4; ++c) acc[a][b][c] = 0.0f;

    const uint32_t* wAh = (const uint32_t*)tAh;
    const uint32_t* wAl = (const uint32_t*)tAl;
    const uint32_t* wBh = (const uint32_t*)tBh;
    const uint32_t* wBl = (const uint32_t*)tBl;

    for (int ch = 0; ch < K / 64; ++ch) {
        const int k0 = ch * 64;
#pragma unroll 4
        for (int i = tid; i < 1024; i += 256) {
            int r = i >> 3, cc = i & 7;
            size_t aofs = (size_t)(m0 + r) * K + k0 + cc * 8;
            size_t bofs = (size_t)(n0 + r) * K + k0 + cc * 8;
            *(uint4*)(tAh + r * 144 + cc * 16) = *(const uint4*)(Ah + aofs);
            *(uint4*)(tAl + r * 144 + cc * 16) = *(const uint4*)(Al + aofs);
            *(uint4*)(tBh + r * 144 + cc * 16) = *(const uint4*)(Bh + bofs);
            *(uint4*)(tBl + r * 144 + cc * 16) = *(const uint4*)(Bl + bofs);
        }
        __syncthreads();

#pragma unroll
        for (int ks = 0; ks < 4; ++ks) {
            uint32_t fah[4][4], fal[4][4];
#pragma unroll
            for (int mt = 0; mt < 4; ++mt) {
                int rr = wm * 64 + mt * 16 + g;
                int o0 = rr * 36 + ks * 8 + tg;
                int o1 = (rr + 8) * 36 + ks * 8 + tg;
                fah[mt][0] = wAh[o0];     fah[mt][1] = wAh[o1];
                fah[mt][2] = wAh[o0 + 4]; fah[mt][3] = wAh[o1 + 4];
                fal[mt][0] = wAl[o0];     fal[mt][1] = wAl[o1];
                fal[mt][2] = wAl[o0 + 4]; fal[mt][3] = wAl[o1 + 4];
            }
            uint32_t fbh[4][2], fbl[4][2];
#pragma unroll
            for (int nt = 0; nt < 4; ++nt) {
                int cc = wn * 32 + nt * 8 + g;
                int o  = cc * 36 + ks * 8 + tg;
                fbh[nt][0] = wBh[o]; fbh[nt][1] = wBh[o + 4];
                fbl[nt][0] = wBl[o]; fbl[nt][1] = wBl[o + 4];
            }
#pragma unroll
            for (int mt = 0; mt < 4; ++mt)
#pragma unroll
                for (int nt = 0; nt < 4; ++nt) {
                    mma16816(acc[mt][nt], fah[mt], fbh[nt]);
                    mma16816(acc[mt][nt], fah[mt], fbl[nt]);
                    mma16816(acc[mt][nt], fal[mt], fbh[nt]);
                }
        }
        __syncthreads();
    }

    // epilogue
#pragma unroll
    for (int mt = 0; mt < 4; ++mt) {
#pragma unroll
        for (int nt = 0; nt < 4; ++nt) {
            int rr = m0 + wm * 64 + mt * 16 + g;
            int cc = n0 + wn * 32 + nt * 8 + tg * 2;
            float b0 = bias[cc], b1 = bias[cc + 1];
            float v00 = acc[mt][nt][0] + b0, v01 = acc[mt][nt][1] + b1;
            float v10 = acc[mt][nt][2] + b0, v11 = acc[mt][nt][3] + b1;
            if (Cf) {
                *(float2*)&Cf[(size_t)rr * N + cc]       = make_float2(v00, v01);
                *(float2*)&Cf[(size_t)(rr + 8) * N + cc] = make_float2(v10, v11);
            }
            if (Chi) {
                uint32_t h, l;
                split2(v00, v01, h, l);
                *(uint32_t*)&Chi[(size_t)rr * N + cc] = h;
                *(uint32_t*)&Clo[(size_t)rr * N + cc] = l;
                split2(v10, v11, h, l);
                *(uint32_t*)&Chi[(size_t)(rr + 8) * N + cc] = h;
                *(uint32_t*)&Clo[(size_t)(rr + 8) * N + cc] = l;
            }
        }
    }
}

// ---------------------------------------------------------------------------
// HMMA flash attention. CTA per (b, h, 64-query block). 4 warps (128 thr).
// Q fragments in registers; K tiles [kpos][d] pitch 72; V transposed
// [d][kpos] pitch 74. S c-frags reused as A-frags of P@V. 3-term split
// precision on both matmuls.
// ---------------------------------------------------------------------------
#define KW 36     // K/Q tile word pitch (72 bf16)
#define VW 37     // Vt tile word pitch  (74 bf16)

__global__ __launch_bounds__(128)
void attn_kernel(const bf16* __restrict__ qh, const bf16* __restrict__ ql,
                 bf16* __restrict__ outh, bf16* __restrict__ outl)
{
    __shared__ __align__(16) uint32_t sA[2 * 64 * KW + 2 * 64 * VW];
    uint32_t* wKh  = sA;
    uint32_t* wKl  = sA + 64 * KW;
    uint32_t* wVth = sA + 2 * 64 * KW;
    uint32_t* wVtl = sA + 2 * 64 * KW + 64 * VW;
    ushort_t* uVth = (ushort_t*)wVth;
    ushort_t* uVtl = (ushort_t*)wVtl;

    const int tid = threadIdx.x;
    const int w   = tid >> 5, lane = tid & 31;
    const int g   = lane >> 2, tg = lane & 3;
    const int bh  = blockIdx.y;
    const int b   = bh >> 4, h = bh & 15;
    const int qb  = blockIdx.x;
    const float scale = 0.125f;   // 1/sqrt(64)

    const size_t rs = 3 * DIM;                 // qkv row stride (bf16 elements)
    const size_t tokbase = (size_t)b * SEQ;

    // ---- stage Q tile into K-tile smem, load fragments ----
#pragma unroll 4
    for (int i = tid; i < 512; i += 128) {
        int r = i >> 3, c = i & 7;
        size_t go = (tokbase + qb * 64 + r) * rs + h * 64 + c * 8;
        *(uint4*)((char*)wKh + r * 144 + c * 16) = *(const uint4*)(qh + go);
        *(uint4*)((char*)wKl + r * 144 + c * 16) = *(const uint4*)(ql + go);
    }
    __syncthreads();

    uint32_t fqh[4][4], fql[4][4];
#pragma unroll
    for (int ks = 0; ks < 4; ++ks) {
        int rr = w * 16 + g;
        int o0 = rr * KW + ks * 8 + tg;
        int o1 = (rr + 8) * KW + ks * 8 + tg;
        fqh[ks][0] = wKh[o0];     fqh[ks][1] = wKh[o1];
        fqh[ks][2] = wKh[o0 + 4]; fqh[ks][3] = wKh[o1 + 4];
        fql[ks][0] = wKl[o0];     fql[ks][1] = wKl[o1];
        fql[ks][2] = wKl[o0 + 4]; fql[ks][3] = wKl[o1 + 4];
    }
    __syncthreads();

    float m0 = -1e30f, m1 = -1e30f, l0 = 0.0f, l1 = 0.0f;
    float o[8][4];
#pragma unroll
    for (int nt = 0; nt < 8; ++nt)
#pragma unroll
        for (int j = 0; j < 4; ++j) o[nt][j] = 0.0f;

    for (int kb = 0; kb < SEQ / 64; ++kb) {
        // ---- load K hi/lo, V hi/lo (transposed) ----
#pragma unroll 4
        for (int i = tid; i < 512; i += 128) {
            int r = i >> 3, c = i & 7;
            size_t gk = (tokbase + kb * 64 + r) * rs + DIM + h * 64 + c * 8;
            *(uint4*)((char*)wKh + r * 144 + c * 16) = *(const uint4*)(qh + gk);
            *(uint4*)((char*)wKl + r * 144 + c * 16) = *(const uint4*)(ql + gk);
            size_t gv = (tokbase + kb * 64 + r) * rs + 2 * DIM + h * 64 + c * 8;
            uint4 vh = *(const uint4*)(qh + gv);
            uint4 vl = *(const uint4*)(ql + gv);
            uint32_t vhw[4] = {vh.x, vh.y, vh.z, vh.w};
            uint32_t vlw[4] = {vl.x, vl.y, vl.z, vl.w};
#pragma unroll
            for (int j = 0; j < 8; ++j) {
                int d = c * 8 + j;
                uVth[d * 74 + r] = (ushort_t)(vhw[j >> 1] >> ((j & 1) * 16));
                uVtl[d * 74 + r] = (ushort_t)(vlw[j >> 1] >> ((j & 1) * 16));
            }
        }
        __syncthreads();

        // ---- S = Q K^T (3-term) ----
        float s[8][4];
#pragma unroll
        for (int nt = 0; nt < 8; ++nt)
#pragma unroll
            for (int j = 0; j < 4; ++j) s[nt][j] = 0.0f;

#pragma unroll
        for (int nt = 0; nt < 8; ++nt) {
#pragma unroll
            for (int ks = 0; ks < 4; ++ks) {
                int oo = (nt * 8 + g) * KW + ks * 8 + tg;
                uint32_t bkh[2] = {wKh[oo], wKh[oo + 4]};
                uint32_t bkl[2] = {wKl[oo], wKl[oo + 4]};
                mma16816(s[nt], fqh[ks], bkh);
                mma16816(s[nt], fqh[ks], bkl);
                mma16816(s[nt], fql[ks], bkh);
            }
        }

        // ---- online softmax ----
        float mx0 = -1e30f, mx1 = -1e30f;
#pragma unroll
        for (int nt = 0; nt < 8; ++nt) {
#pragma unroll
            for (int j = 0; j < 4; ++j) s[nt][j] *= scale;
            mx0 = fmaxf(mx0, fmaxf(s[nt][0], s[nt][1]));
            mx1 = fmaxf(mx1, fmaxf(s[nt][2], s[nt][3]));
        }
        mx0 = fmaxf(mx0, __shfl_xor_sync(0xffffffffu, mx0, 1));
        mx0 = fmaxf(mx0, __shfl_xor_sync(0xffffffffu, mx0, 2));
        mx1 = fmaxf(mx1, __shfl_xor_sync(0xffffffffu, mx1, 1));
        mx1 = fmaxf(mx1, __shfl_xor_sync(0xffffffffu, mx1, 2));

        float nm0 = fmaxf(m0, mx0), nm1 = fmaxf(m1, mx1);
        float a0 = __expf(m0 - nm0), a1 = __expf(m1 - nm1);
        m0 = nm0; m1 = nm1;

        float sum0 = 0.0f, sum1 = 0.0f;
#pragma unroll
        for (int nt = 0; nt < 8; ++nt) {
            s[nt][0] = __expf(s[nt][0] - nm0);
            s[nt][1] = __expf(s[nt][1] - nm0);
            s[nt][2] = __expf(s[nt][2] - nm1);
            s[nt][3] = __expf(s[nt][3] - nm1);
            sum0 += s[nt][0] + s[nt][1];
            sum1 += s[nt][2] + s[nt][3];
        }
        sum0 += __shfl_xor_sync(0xffffffffu, sum0, 1);
        sum0 += __shfl_xor_sync(0xffffffffu, sum0, 2);
        sum1 += __shfl_xor_sync(0xffffffffu, sum1, 1);
        sum1 += __shfl_xor_sync(0xffffffffu, sum1, 2);
        l0 = l0 * a0 + sum0;
        l1 = l1 * a1 + sum1;

#pragma unroll
        for (int nt = 0; nt < 8; ++nt) {
            o[nt][0] *= a0; o[nt][1] *= a0;
            o[nt][2] *= a1; o[nt][3] *= a1;
        }

        // ---- O += P V (3-term; P split hi/lo, c-frag -> a-frag reuse) ----
#pragma unroll
        for (int ks = 0; ks < 4; ++ks) {
            int t0 = 2 * ks, t1 = 2 * ks + 1;
            uint32_t pah[4], pal[4];
            split2(s[t0][0], s[t0][1], pah[0], pal[0]);
            split2(s[t0][2], s[t0][3], pah[1], pal[1]);
            split2(s[t1][0], s[t1][1], pah[2], pal[2]);
            split2(s[t1][2], s[t1][3], pah[3], pal[3]);
#pragma unroll
            for (int nt = 0; nt < 8; ++nt) {
                int oo = (nt * 8 + g) * VW + ks * 8 + tg;
                uint32_t bvh[2] = {wVth[oo], wVth[oo + 4]};
                uint32_t bvl[2] = {wVtl[oo], wVtl[oo + 4]};
                mma16816(o[nt], pah, bvh);
                mma16816(o[nt], pah, bvl);
                mma16816(o[nt], pal, bvh);
            }
        }
        __syncthreads();
    }

    // ---- epilogue: normalize, split to hi/lo bf16, store [token][1024] ----
    float inv0 = 1.0f / l0, inv1 = 1.0f / l1;
    size_t row0 = tokbase + qb * 64 + w * 16 + g;
    size_t row1 = row0 + 8;
#pragma unroll
    for (int nt = 0; nt < 8; ++nt) {
        int cc = h * 64 + nt * 8 + tg * 2;
        uint32_t hh, ll;
        split2(o[nt][0] * inv0, o[nt][1] * inv0, hh, ll);
        *(uint32_t*)&outh[row0 * DIM + cc] = hh;
        *(uint32_t*)&outl[row0 * DIM + cc] = ll;
        split2(o[nt][2] * inv1, o[nt][3] * inv1, hh, ll);
        *(uint32_t*)&outh[row1 * DIM + cc] = hh;
        *(uint32_t*)&outl[row1 * DIM + cc] = ll;
    }
}

// ---------------------------------------------------------------------------
extern "C" void kernel_launch(void* const* d_in, const int* in_sizes, int n_in,
                              void* d_out, int out_size)
{
    const float* x      = (const float*)d_in[0];
    const float* W_qkv  = (const float*)d_in[1];
    const float* b_qkv  = (const float*)d_in[2];
    const float* W_proj = (const float*)d_in[3];
    const float* b_proj = (const float*)d_in[4];
    float* out = (float*)d_out;

    bf16 *qh, *ql, *ah, *al, *bh, *bl;
    cudaGetSymbolAddress((void**)&qh, g_qh);
    cudaGetSymbolAddress((void**)&ql, g_ql);
    cudaGetSymbolAddress((void**)&ah, g_ah);
    cudaGetSymbolAddress((void**)&al, g_al);
    cudaGetSymbolAddress((void**)&bh, g_bh);
    cudaGetSymbolAddress((void**)&bl, g_bl);

    cudaFuncSetAttribute(hmma_gemm, cudaFuncAttributeMaxDynamicSharedMemorySize, GEMM_SMEM);

    // 1) split x -> bf16 hi/lo ; W_qkv^T hi/lo
    split_kernel<<<(NTOK * DIM / 4 + 255) / 256, 256>>>(x, ah, al, NTOK * DIM / 4);
    splitT_kernel<<<dim3(3 * DIM / 32, DIM / 32), dim3(32, 8)>>>(W_qkv, bh, bl, DIM, 3 * DIM);

    // 2) QKV projection -> qkv hi/lo bf16 directly (no fp32 intermediate)
    hmma_gemm<<<dim3(3 * DIM / 128, NTOK / 128), 256, GEMM_SMEM>>>(
        ah, al, bh, bl, b_qkv, nullptr, qh, ql, NTOK, 3 * DIM, DIM);

    // 3) flash attention -> hi/lo bf16 output (into g_ah/g_al)
    attn_kernel<<<dim3(SEQ / 64, BATCH * NH), 128>>>(qh, ql, ah, al);

    // 4) W_proj^T hi/lo
    splitT_kernel<<<dim3(DIM / 32, DIM / 32), dim3(32, 8)>>>(W_proj, bh, bl, DIM, DIM);

    // 5) output projection -> fp32 out
    hmma_gemm<<<dim3(DIM / 128, NTOK / 128), 256, GEMM_SMEM>>>(
        ah, al, bh, bl, b_proj, out, nullptr, nullptr, NTOK, DIM, DIM);
}

// round 11
// speedup vs baseline: 4.9714x; 1.1742x over previous
#include <cuda_runtime.h>
#include <cuda_bf16.h>
#include <math.h>
#include <cstdint>

#define BATCH 2
#define SEQ   2048
#define DIM   1024
#define NH    16
#define HD    64
#define NTOK  4096

typedef __nv_bfloat16 bf16;

// ---------------------------------------------------------------------------
// Scratch (__device__ globals; no allocation)
// ---------------------------------------------------------------------------
__device__ bf16 g_qh[(size_t)NTOK * 3 * DIM];   // qkv hi  [4096,3072]
__device__ bf16 g_ql[(size_t)NTOK * 3 * DIM];   // qkv lo
__device__ bf16 g_ah[(size_t)NTOK * DIM];       // GEMM A hi / attn out hi
__device__ bf16 g_al[(size_t)NTOK * DIM];       // GEMM A lo / attn out lo
__device__ bf16 g_bh[(size_t)3 * DIM * DIM];    // W^T hi [N,K]
__device__ bf16 g_bl[(size_t)3 * DIM * DIM];    // W^T lo

// ---------------------------------------------------------------------------
// MMA / LDSM primitives (arch-neutral, OK on compute_103 base target)
// ---------------------------------------------------------------------------
__device__ __forceinline__ void mma16816(float* c, const uint32_t* a, const uint32_t* b) {
    asm volatile(
        "mma.sync.aligned.m16n8k16.row.col.f32.bf16.bf16.f32 "
        "{%0,%1,%2,%3}, {%4,%5,%6,%7}, {%8,%9}, {%0,%1,%2,%3};"
        : "+f"(c[0]), "+f"(c[1]), "+f"(c[2]), "+f"(c[3])
        : "r"(a[0]), "r"(a[1]), "r"(a[2]), "r"(a[3]), "r"(b[0]), "r"(b[1]));
}
__device__ __forceinline__ uint32_t cvta_smem(const void* p) {
    uint32_t a;
    asm("{ .reg .u64 t; cvta.to.shared.u64 t, %1; cvt.u32.u64 %0, t; }" : "=r"(a) : "l"(p));
    return a;
}
__device__ __forceinline__ void ldsm_x4(uint32_t* r, uint32_t addr) {
    asm volatile("ldmatrix.sync.aligned.m8n8.x4.shared.b16 {%0,%1,%2,%3}, [%4];"
                 : "=r"(r[0]), "=r"(r[1]), "=r"(r[2]), "=r"(r[3]) : "r"(addr));
}
__device__ __forceinline__ void ldsm_x4_t(uint32_t* r, uint32_t addr) {
    asm volatile("ldmatrix.sync.aligned.m8n8.x4.trans.shared.b16 {%0,%1,%2,%3}, [%4];"
                 : "=r"(r[0]), "=r"(r[1]), "=r"(r[2]), "=r"(r[3]) : "r"(addr));
}

__device__ __forceinline__ void split2(float x, float y, uint32_t& hi, uint32_t& lo) {
    __nv_bfloat16 hx = __float2bfloat16(x);
    __nv_bfloat16 hy = __float2bfloat16(y);
    __nv_bfloat162 h2(hx, hy);
    __nv_bfloat162 l2(__float2bfloat16(x - __bfloat162float(hx)),
                      __float2bfloat16(y - __bfloat162float(hy)));
    hi = *(uint32_t*)&h2;
    lo = *(uint32_t*)&l2;
}

// ---------------------------------------------------------------------------
// fp32 -> bf16 hi/lo elementwise split
// ---------------------------------------------------------------------------
__global__ __launch_bounds__(256)
void split_kernel(const float* __restrict__ in, bf16* __restrict__ hi,
                  bf16* __restrict__ lo, int n4)
{
    int i = blockIdx.x * blockDim.x + threadIdx.x;
    if (i >= n4) return;
    float4 v = *(const float4*)&in[i * 4];
    uint32_t h01, l01, h23, l23;
    split2(v.x, v.y, h01, l01);
    split2(v.z, v.w, h23, l23);
    *(uint32_t*)&hi[i * 4]     = h01;
    *(uint32_t*)&hi[i * 4 + 2] = h23;
    *(uint32_t*)&lo[i * 4]     = l01;
    *(uint32_t*)&lo[i * 4 + 2] = l23;
}

// W[K,N] fp32 -> hi/lo [N,K] bf16 (transpose + split)
__global__ __launch_bounds__(256)
void splitT_kernel(const float* __restrict__ W, bf16* __restrict__ hi,
                   bf16* __restrict__ lo, int K, int N)
{
    __shared__ float t[32][33];
    const int n0 = blockIdx.x * 32, k0 = blockIdx.y * 32;
    const int tx = threadIdx.x, ty = threadIdx.y;
#pragma unroll
    for (int r = 0; r < 4; ++r)
        t[ty + r * 8][tx] = W[(size_t)(k0 + ty + r * 8) * N + n0 + tx];
    __syncthreads();
#pragma unroll
    for (int r = 0; r < 4; ++r) {
        int nl = ty + r * 8;
        float x = t[tx][nl];
        __nv_bfloat16 h = __float2bfloat16(x);
        __nv_bfloat16 l = __float2bfloat16(x - __bfloat162float(h));
        size_t o = (size_t)(n0 + nl) * K + k0 + tx;
        hi[o] = h; lo[o] = l;
    }
}

// ---------------------------------------------------------------------------
// HMMA split-bf16 GEMM with ldmatrix fragment loads.
// C[M,N] = A@W + bias.  A:[M,K] hi/lo, B=W^T:[N,K] hi/lo.
// CTA 128x128, BK=64, 256 threads, warp tile 64x32. Pitch 144B (36 words).
// ---------------------------------------------------------------------------
#define GEMM_SMEM (4 * 128 * 144)   // 73728 B

__global__ __launch_bounds__(256)
void hmma_gemm(const bf16* __restrict__ Ah, const bf16* __restrict__ Al,
               const bf16* __restrict__ Bh, const bf16* __restrict__ Bl,
               const float* __restrict__ bias,
               float* __restrict__ Cf, bf16* __restrict__ Chi, bf16* __restrict__ Clo,
               int M, int N, int K)
{
    extern __shared__ char sm[];
    char* tAh = sm;
    char* tAl = sm + 128 * 144;
    char* tBh = sm + 2 * 128 * 144;
    char* tBl = sm + 3 * 128 * 144;

    const int tid = threadIdx.x;
    const int w   = tid >> 5, lane = tid & 31;
    const int g   = lane >> 2, tg = lane & 3;
    const int grp = lane >> 3, ri = lane & 7;
    const int wm  = w & 1;        // 64-row block
    const int wn  = w >> 1;       // 32-col block
    const int m0  = blockIdx.y * 128, n0 = blockIdx.x * 128;

    // per-lane ldsm address components
    const uint32_t sAh = cvta_smem(tAh), sAl = cvta_smem(tAl);
    const uint32_t sBh = cvta_smem(tBh), sBl = cvta_smem(tBl);
    // A-frag: row = (grp&1)*8+ri, byte = ((grp>>1)&1)*16
    const uint32_t aLane = (uint32_t)(((grp & 1) * 8 + ri) * 144 + ((grp >> 1) & 1) * 16);
    // B-frag: row = ((grp>>1)&1)*8+ri, byte = (grp&1)*16
    const uint32_t bLane = (uint32_t)((((grp >> 1) & 1) * 8 + ri) * 144 + (grp & 1) * 16);

    float acc[4][4][4];
#pragma unroll
    for (int a = 0; a < 4; ++a)
#pragma unroll
        for (int b = 0; b < 4; ++b)
#pragma unroll
            for (int c = 0; c < 4; ++c) acc[a][b][c] = 0.0f;

    for (int ch = 0; ch < K / 64; ++ch) {
        const int k0 = ch * 64;
#pragma unroll 4
        for (int i = tid; i < 1024; i += 256) {
            int r = i >> 3, cc = i & 7;
            size_t aofs = (size_t)(m0 + r) * K + k0 + cc * 8;
            size_t bofs = (size_t)(n0 + r) * K + k0 + cc * 8;
            *(uint4*)(tAh + r * 144 + cc * 16) = *(const uint4*)(Ah + aofs);
            *(uint4*)(tAl + r * 144 + cc * 16) = *(const uint4*)(Al + aofs);
            *(uint4*)(tBh + r * 144 + cc * 16) = *(const uint4*)(Bh + bofs);
            *(uint4*)(tBl + r * 144 + cc * 16) = *(const uint4*)(Bl + bofs);
        }
        __syncthreads();

#pragma unroll
        for (int ks = 0; ks < 4; ++ks) {
            uint32_t fah[4][4], fal[4][4];
#pragma unroll
            for (int mt = 0; mt < 4; ++mt) {
                uint32_t ro = (uint32_t)((wm * 64 + mt * 16) * 144 + ks * 32) + aLane;
                ldsm_x4(fah[mt], sAh + ro);
                ldsm_x4(fal[mt], sAl + ro);
            }
            uint32_t fbh[2][4], fbl[2][4];
#pragma unroll
            for (int ntp = 0; ntp < 2; ++ntp) {
                uint32_t ro = (uint32_t)((wn * 32 + ntp * 16) * 144 + ks * 32) + bLane;
                ldsm_x4(fbh[ntp], sBh + ro);
                ldsm_x4(fbl[ntp], sBl + ro);
            }
#pragma unroll
            for (int mt = 0; mt < 4; ++mt)
#pragma unroll
                for (int nt = 0; nt < 4; ++nt) {
                    const uint32_t* bh2 = fbh[nt >> 1] + (nt & 1) * 2;
                    const uint32_t* bl2 = fbl[nt >> 1] + (nt & 1) * 2;
                    mma16816(acc[mt][nt], fah[mt], bh2);
                    mma16816(acc[mt][nt], fah[mt], bl2);
                    mma16816(acc[mt][nt], fal[mt], bh2);
                }
        }
        __syncthreads();
    }

    // epilogue
#pragma unroll
    for (int mt = 0; mt < 4; ++mt) {
#pragma unroll
        for (int nt = 0; nt < 4; ++nt) {
            int rr = m0 + wm * 64 + mt * 16 + g;
            int cc = n0 + wn * 32 + nt * 8 + tg * 2;
            float b0 = bias[cc], b1 = bias[cc + 1];
            float v00 = acc[mt][nt][0] + b0, v01 = acc[mt][nt][1] + b1;
            float v10 = acc[mt][nt][2] + b0, v11 = acc[mt][nt][3] + b1;
            if (Cf) {
                *(float2*)&Cf[(size_t)rr * N + cc]       = make_float2(v00, v01);
                *(float2*)&Cf[(size_t)(rr + 8) * N + cc] = make_float2(v10, v11);
            }
            if (Chi) {
                uint32_t h, l;
                split2(v00, v01, h, l);
                *(uint32_t*)&Chi[(size_t)rr * N + cc] = h;
                *(uint32_t*)&Clo[(size_t)rr * N + cc] = l;
                split2(v10, v11, h, l);
                *(uint32_t*)&Chi[(size_t)(rr + 8) * N + cc] = h;
                *(uint32_t*)&Clo[(size_t)(rr + 8) * N + cc] = l;
            }
        }
    }
}

// ---------------------------------------------------------------------------
// HMMA flash attention, ldmatrix edition.
// CTA per (b, h, 64-query block), 4 warps. K row-major [kpos][d]; V row-major
// [kpos][d] with ldmatrix.trans providing P@V B-fragments (no transpose store).
// 3-term split precision on both matmuls.
// ---------------------------------------------------------------------------
__global__ __launch_bounds__(128)
void attn_kernel(const bf16* __restrict__ qh, const bf16* __restrict__ ql,
                 bf16* __restrict__ outh, bf16* __restrict__ outl)
{
    __shared__ __align__(16) char sA[4 * 64 * 144];
    char* tKh = sA;
    char* tKl = sA + 64 * 144;
    char* tVh = sA + 2 * 64 * 144;
    char* tVl = sA + 3 * 64 * 144;

    const int tid = threadIdx.x;
    const int w   = tid >> 5, lane = tid & 31;
    const int g   = lane >> 2, tg = lane & 3;
    const int grp = lane >> 3, ri = lane & 7;
    const int bh  = blockIdx.y;
    const int b   = bh >> 4, h = bh & 15;
    const int qb  = blockIdx.x;
    const float scale = 0.125f;   // 1/sqrt(64)

    const size_t rs = 3 * DIM;
    const size_t tokbase = (size_t)b * SEQ;

    const uint32_t sKh = cvta_smem(tKh), sKl = cvta_smem(tKl);
    const uint32_t sVh = cvta_smem(tVh), sVl = cvta_smem(tVl);
    // A-frag lane offset (also used for Q): row=(grp&1)*8+ri, byte=((grp>>1)&1)*16
    const uint32_t aLane = (uint32_t)(((grp & 1) * 8 + ri) * 144 + ((grp >> 1) & 1) * 16);
    // K B-frag lane offset: row=((grp>>1)&1)*8+ri, byte=(grp&1)*16
    const uint32_t kLane = (uint32_t)((((grp >> 1) & 1) * 8 + ri) * 144 + (grp & 1) * 16);
    // V trans B-frag lane offset: row=(grp&1)*8+ri, byte=((grp>>1)&1)*16
    const uint32_t vLane = aLane;

    // ---- stage Q (hi->tKh, lo->tKl), load fragments via ldsm ----
#pragma unroll 4
    for (int i = tid; i < 512; i += 128) {
        int r = i >> 3, c = i & 7;
        size_t go = (tokbase + qb * 64 + r) * rs + h * 64 + c * 8;
        *(uint4*)(tKh + r * 144 + c * 16) = *(const uint4*)(qh + go);
        *(uint4*)(tKl + r * 144 + c * 16) = *(const uint4*)(ql + go);
    }
    __syncthreads();

    uint32_t fqh[4][4], fql[4][4];
#pragma unroll
    for (int ks = 0; ks < 4; ++ks) {
        uint32_t ro = (uint32_t)(w * 16 * 144 + ks * 32) + aLane;
        ldsm_x4(fqh[ks], sKh + ro);
        ldsm_x4(fql[ks], sKl + ro);
    }
    __syncthreads();

    float m0 = -1e30f, m1 = -1e30f, l0 = 0.0f, l1 = 0.0f;
    float o[8][4];
#pragma unroll
    for (int nt = 0; nt < 8; ++nt)
#pragma unroll
        for (int j = 0; j < 4; ++j) o[nt][j] = 0.0f;

    for (int kb = 0; kb < SEQ / 64; ++kb) {
        // ---- load K,V (both row-major, vectorized) ----
#pragma unroll 4
        for (int i = tid; i < 512; i += 128) {
            int r = i >> 3, c = i & 7;
            size_t gk = (tokbase + kb * 64 + r) * rs + DIM + h * 64 + c * 8;
            size_t gv = gk + DIM;
            *(uint4*)(tKh + r * 144 + c * 16) = *(const uint4*)(qh + gk);
            *(uint4*)(tKl + r * 144 + c * 16) = *(const uint4*)(ql + gk);
            *(uint4*)(tVh + r * 144 + c * 16) = *(const uint4*)(qh + gv);
            *(uint4*)(tVl + r * 144 + c * 16) = *(const uint4*)(ql + gv);
        }
        __syncthreads();

        // ---- S = Q K^T (3-term), ldsm.x4 gives 2 n-blocks per load ----
        float s[8][4];
#pragma unroll
        for (int nt = 0; nt < 8; ++nt)
#pragma unroll
            for (int j = 0; j < 4; ++j) s[nt][j] = 0.0f;

#pragma unroll
        for (int ntp = 0; ntp < 4; ++ntp) {
#pragma unroll
            for (int ks = 0; ks < 4; ++ks) {
                uint32_t ro = (uint32_t)(ntp * 16 * 144 + ks * 32) + kLane;
                uint32_t rh[4], rl[4];
                ldsm_x4(rh, sKh + ro);
                ldsm_x4(rl, sKl + ro);
                mma16816(s[2 * ntp],     fqh[ks], rh);
                mma16816(s[2 * ntp],     fqh[ks], rl);
                mma16816(s[2 * ntp],     fql[ks], rh);
                mma16816(s[2 * ntp + 1], fqh[ks], rh + 2);
                mma16816(s[2 * ntp + 1], fqh[ks], rl + 2);
                mma16816(s[2 * ntp + 1], fql[ks], rh + 2);
            }
        }

        // ---- online softmax ----
        float mx0 = -1e30f, mx1 = -1e30f;
#pragma unroll
        for (int nt = 0; nt < 8; ++nt) {
#pragma unroll
            for (int j = 0; j < 4; ++j) s[nt][j] *= scale;
            mx0 = fmaxf(mx0, fmaxf(s[nt][0], s[nt][1]));
            mx1 = fmaxf(mx1, fmaxf(s[nt][2], s[nt][3]));
        }
        mx0 = fmaxf(mx0, __shfl_xor_sync(0xffffffffu, mx0, 1));
        mx0 = fmaxf(mx0, __shfl_xor_sync(0xffffffffu, mx0, 2));
        mx1 = fmaxf(mx1, __shfl_xor_sync(0xffffffffu, mx1, 1));
        mx1 = fmaxf(mx1, __shfl_xor_sync(0xffffffffu, mx1, 2));

        float nm0 = fmaxf(m0, mx0), nm1 = fmaxf(m1, mx1);
        float a0 = __expf(m0 - nm0), a1 = __expf(m1 - nm1);
        m0 = nm0; m1 = nm1;

        float sum0 = 0.0f, sum1 = 0.0f;
#pragma unroll
        for (int nt = 0; nt < 8; ++nt) {
            s[nt][0] = __expf(s[nt][0] - nm0);
            s[nt][1] = __expf(s[nt][1] - nm0);
            s[nt][2] = __expf(s[nt][2] - nm1);
            s[nt][3] = __expf(s[nt][3] - nm1);
            sum0 += s[nt][0] + s[nt][1];
            sum1 += s[nt][2] + s[nt][3];
        }
        sum0 += __shfl_xor_sync(0xffffffffu, sum0, 1);
        sum0 += __shfl_xor_sync(0xffffffffu, sum0, 2);
        sum1 += __shfl_xor_sync(0xffffffffu, sum1, 1);
        sum1 += __shfl_xor_sync(0xffffffffu, sum1, 2);
        l0 = l0 * a0 + sum0;
        l1 = l1 * a1 + sum1;

#pragma unroll
        for (int nt = 0; nt < 8; ++nt) {
            o[nt][0] *= a0; o[nt][1] *= a0;
            o[nt][2] *= a1; o[nt][3] *= a1;
        }

        // ---- O += P V (3-term), V B-frags via ldsm.x4.trans ----
#pragma unroll
        for (int ks = 0; ks < 4; ++ks) {
            int t0 = 2 * ks, t1 = 2 * ks + 1;
            uint32_t pah[4], pal[4];
            split2(s[t0][0], s[t0][1], pah[0], pal[0]);
            split2(s[t0][2], s[t0][3], pah[1], pal[1]);
            split2(s[t1][0], s[t1][1], pah[2], pal[2]);
            split2(s[t1][2], s[t1][3], pah[3], pal[3]);
#pragma unroll
            for (int ntp = 0; ntp < 4; ++ntp) {
                uint32_t ro = (uint32_t)(ks * 16 * 144 + ntp * 32) + vLane;
                uint32_t bvh[4], bvl[4];
                ldsm_x4_t(bvh, sVh + ro);
                ldsm_x4_t(bvl, sVl + ro);
                mma16816(o[2 * ntp],     pah, bvh);
                mma16816(o[2 * ntp],     pah, bvl);
                mma16816(o[2 * ntp],     pal, bvh);
                mma16816(o[2 * ntp + 1], pah, bvh + 2);
                mma16816(o[2 * ntp + 1], pah, bvl + 2);
                mma16816(o[2 * ntp + 1], pal, bvh + 2);
            }
        }
        __syncthreads();
    }

    // ---- epilogue: normalize, split hi/lo, store [token][1024] ----
    float inv0 = 1.0f / l0, inv1 = 1.0f / l1;
    size_t row0 = tokbase + qb * 64 + w * 16 + g;
    size_t row1 = row0 + 8;
#pragma unroll
    for (int nt = 0; nt < 8; ++nt) {
        int cc = h * 64 + nt * 8 + tg * 2;
        uint32_t hh, ll;
        split2(o[nt][0] * inv0, o[nt][1] * inv0, hh, ll);
        *(uint32_t*)&outh[row0 * DIM + cc] = hh;
        *(uint32_t*)&outl[row0 * DIM + cc] = ll;
        split2(o[nt][2] * inv1, o[nt][3] * inv1, hh, ll);
        *(uint32_t*)&outh[row1 * DIM + cc] = hh;
        *(uint32_t*)&outl[row1 * DIM + cc] = ll;
    }
}

// ---------------------------------------------------------------------------
extern "C" void kernel_launch(void* const* d_in, const int* in_sizes, int n_in,
                              void* d_out, int out_size)
{
    const float* x      = (const float*)d_in[0];
    const float* W_qkv  = (const float*)d_in[1];
    const float* b_qkv  = (const float*)d_in[2];
    const float* W_proj = (const float*)d_in[3];
    const float* b_proj = (const float*)d_in[4];
    float* out = (float*)d_out;

    bf16 *qh, *ql, *ah, *al, *bh, *bl;
    cudaGetSymbolAddress((void**)&qh, g_qh);
    cudaGetSymbolAddress((void**)&ql, g_ql);
    cudaGetSymbolAddress((void**)&ah, g_ah);
    cudaGetSymbolAddress((void**)&al, g_al);
    cudaGetSymbolAddress((void**)&bh, g_bh);
    cudaGetSymbolAddress((void**)&bl, g_bl);

    cudaFuncSetAttribute(hmma_gemm, cudaFuncAttributeMaxDynamicSharedMemorySize, GEMM_SMEM);

    // 1) split x -> bf16 hi/lo ; W_qkv^T hi/lo
    split_kernel<<<(NTOK * DIM / 4 + 255) / 256, 256>>>(x, ah, al, NTOK * DIM / 4);
    splitT_kernel<<<dim3(3 * DIM / 32, DIM / 32), dim3(32, 8)>>>(W_qkv, bh, bl, DIM, 3 * DIM);

    // 2) QKV projection -> qkv hi/lo bf16 directly
    hmma_gemm<<<dim3(3 * DIM / 128, NTOK / 128), 256, GEMM_SMEM>>>(
        ah, al, bh, bl, b_qkv, nullptr, qh, ql, NTOK, 3 * DIM, DIM);

    // 3) flash attention -> hi/lo bf16 output (into g_ah/g_al)
    attn_kernel<<<dim3(SEQ / 64, BATCH * NH), 128>>>(qh, ql, ah, al);

    // 4) W_proj^T hi/lo
    splitT_kernel<<<dim3(DIM / 32, DIM / 32), dim3(32, 8)>>>(W_proj, bh, bl, DIM, DIM);

    // 5) output projection -> fp32 out
    hmma_gemm<<<dim3(DIM / 128, NTOK / 128), 256, GEMM_SMEM>>>(
        ah, al, bh, bl, b_proj, out, nullptr, nullptr, NTOK, DIM, DIM);
}